// round 6
// baseline (speedup 1.0000x reference)
#include <cuda_runtime.h>

// CrimeModelLSTM: 2-layer LSTM (H=8), B=4096, T=512, FC head [4,8].
// R6: 16 threads per element. Thread pair (j, j+8) owns hidden unit j and
// SPLITS the k-summation (half0: k 0..3, half1: k 4..7) for all three weight
// matrices. Partials combined via one shfl_xor(8) exchange. Half0 then runs
// the L1 activation/cell chain, half1 runs L2's — identical instruction
// stream, different data (no divergence). Doubles warps/SMSP (1.73 -> 3.46)
// to fill the issue gaps ncu shows, while halving per-thread FMA work.

typedef unsigned long long u64;

__device__ __forceinline__ u64 pk2(float lo, float hi) {
    u64 r; asm("mov.b64 %0, {%1,%2};" : "=l"(r) : "f"(lo), "f"(hi)); return r;
}
__device__ __forceinline__ void upk(u64 v, float& lo, float& hi) {
    asm("mov.b64 {%0,%1}, %2;" : "=f"(lo), "=f"(hi) : "l"(v));
}
__device__ __forceinline__ u64 fma2(u64 a, u64 b, u64 c) {
    u64 d; asm("fma.rn.f32x2 %0, %1, %2, %3;" : "=l"(d) : "l"(a), "l"(b), "l"(c)); return d;
}
__device__ __forceinline__ u64 mul2(u64 a, u64 b) {
    u64 d; asm("mul.rn.f32x2 %0, %1, %2;" : "=l"(d) : "l"(a), "l"(b)); return d;
}
__device__ __forceinline__ u64 add2(u64 a, u64 b) {
    u64 d; asm("add.rn.f32x2 %0, %1, %2;" : "=l"(d) : "l"(a), "l"(b)); return d;
}
__device__ __forceinline__ float tanhap(float x) {
    float r; asm("tanh.approx.f32 %0, %1;" : "=f"(r) : "f"(x)); return r;
}
// input pre-scaled by 0.5: sigmoid(2p) = 0.5 + 0.5*tanh(p)
__device__ __forceinline__ float sig_h(float p) { return fmaf(tanhap(p), 0.5f, 0.5f); }

// 64-bit shuffle helpers (2x 32-bit shfl)
__device__ __forceinline__ u64 shflx8_u64(u64 v) {
    float lo, hi; upk(v, lo, hi);
    lo = __shfl_xor_sync(0xffffffffu, lo, 8, 16);
    hi = __shfl_xor_sync(0xffffffffu, hi, 8, 16);
    return pk2(lo, hi);
}

__global__ void __launch_bounds__(32)
lstm2_kernel(const float* __restrict__ x,
             const float* __restrict__ Wih1, const float* __restrict__ Whh1,
             const float* __restrict__ bih1, const float* __restrict__ bhh1,
             const float* __restrict__ Wih2, const float* __restrict__ Whh2,
             const float* __restrict__ bih2, const float* __restrict__ bhh2,
             const float* __restrict__ Wfc,  const float* __restrict__ bfc,
             float* __restrict__ out)
{
    constexpr int T = 512;
    constexpr int H = 8;

    const int tid  = blockIdx.x * 32 + threadIdx.x;
    const int e    = tid >> 4;            // batch element (16 threads each)
    const int l16  = threadIdx.x & 15;    // lane within 16-group
    const int j    = l16 & 7;             // hidden unit owned
    const bool hi8 = (l16 & 8) != 0;      // half 1?
    const int k0   = hi8 ? 4 : 0;         // this thread's k-range start
    // shuffle source bases for broadcast (h1 lives on lanes 0-7, h2 on 8-15)
    const int s1 = k0;        // h1[k0+i] at lane k0+i
    const int s2 = 8 + k0;    // h2[k0+i] at lane 8+k0+i

    // per-gate scales: sigmoid rows (i,f,o) get 0.5 folded; tanh row (g) 1.0
    const float gsc[4] = {0.5f, 0.5f, 1.0f, 0.5f};

    // ---- weights: unit-j gate rows, k-slice [k0, k0+4), packed (i,f)/(g,o) ----
    u64 wh1p[2][4], wi2p[2][4], wh2p[2][4];
    u64 wx1p[2], bb1p[2], bb2p[2];
    #pragma unroll
    for (int p = 0; p < 2; p++) {
        const int gA = 2 * p, gB = 2 * p + 1;
        const int rA = gA * 8 + j, rB = gB * 8 + j;
        const float sA = gsc[gA], sB = gsc[gB];
        wx1p[p] = pk2(Wih1[rA] * sA, Wih1[rB] * sB);
        bb1p[p] = pk2((bih1[rA] + bhh1[rA]) * sA, (bih1[rB] + bhh1[rB]) * sB);
        bb2p[p] = pk2((bih2[rA] + bhh2[rA]) * sA, (bih2[rB] + bhh2[rB]) * sB);
        #pragma unroll
        for (int i = 0; i < 4; i++) {
            const int k = k0 + i;
            wh1p[p][i] = pk2(Whh1[rA * H + k] * sA, Whh1[rB * H + k] * sB);
            wi2p[p][i] = pk2(Wih2[rA * H + k] * sA, Wih2[rB * H + k] * sB);
            wh2p[p][i] = pk2(Whh2[rA * H + k] * sA, Whh2[rB * H + k] * sB);
        }
    }

    // ---- state: h slices dup-packed; c = c1 on half0, c2 on half1 ----
    u64 h1p[4], h2p[4];
    #pragma unroll
    for (int i = 0; i < 4; i++) { h1p[i] = 0ull; h2p[i] = 0ull; }
    float c = 0.0f;

    const float4* __restrict__ xp = reinterpret_cast<const float4*>(x + (long)e * T);
    float4 xv = xp[0];

    // ---- prologue: L1 step 0 (h=0: x-term only). All threads compute it;
    //      c1 result kept only on half0 (half1's c stays 0 = c2 init).
    {
        u64 x2 = pk2(xv.x, xv.x);
        u64 P0 = fma2(wx1p[0], x2, bb1p[0]);
        u64 P1 = fma2(wx1p[1], x2, bb1p[1]);
        float a, b;
        upk(P0, a, b); const float i1 = sig_h(a), f1 = sig_h(b);
        upk(P1, a, b); const float g1 = tanhap(a), o1 = sig_h(b);
        const float c1_0 = fmaf(f1, 0.0f, i1 * g1);
        const float h1o  = o1 * tanhap(c1_0);
        if (!hi8) c = c1_0;
        #pragma unroll
        for (int i = 0; i < 4; i++) {
            const float v = __shfl_sync(0xffffffffu, h1o, s1 + i, 16);
            h1p[i] = pk2(v, v);
        }
    }

    // ---- main loop: body computes L2(t) and L1(t+1); both consume h1(t) ----
    for (int tt = 0; tt < T / 4; ++tt) {
        const int nxt = (tt + 1 < T / 4) ? (tt + 1) : tt;
        float4 xn = xp[nxt];
        float xs[4] = {xv.y, xv.z, xv.w, xn.x};  // x for L1 step t+1

        #pragma unroll
        for (int q = 0; q < 4; q++) {
            u64 x2 = pk2(xs[q], xs[q]);

            // partial accumulators over this thread's k-slice
            // half0 seeds with bias/x-term; half1 seeds with plain product
            u64 P1_0, P1_1, P2_0, P2_1;
            if (!hi8) {
                P1_0 = fma2(wx1p[0], x2, bb1p[0]);
                P1_1 = fma2(wx1p[1], x2, bb1p[1]);
                P2_0 = bb2p[0];
                P2_1 = bb2p[1];
                P2_0 = fma2(wi2p[0][0], h1p[0], P2_0);
                P2_1 = fma2(wi2p[1][0], h1p[0], P2_1);
            } else {
                P1_0 = mul2(wh1p[0][0], h1p[0]);
                P1_1 = mul2(wh1p[1][0], h1p[0]);
                P2_0 = mul2(wi2p[0][0], h1p[0]);
                P2_1 = mul2(wi2p[1][0], h1p[0]);
            }
            if (!hi8) {
                P1_0 = fma2(wh1p[0][0], h1p[0], P1_0);
                P1_1 = fma2(wh1p[1][0], h1p[0], P1_1);
            }
            #pragma unroll
            for (int i = 1; i < 4; i++) {
                const u64 h = h1p[i];
                P2_0 = fma2(wi2p[0][i], h, P2_0);
                P2_1 = fma2(wi2p[1][i], h, P2_1);
                P1_0 = fma2(wh1p[0][i], h, P1_0);
                P1_1 = fma2(wh1p[1][i], h, P1_1);
            }
            #pragma unroll
            for (int i = 0; i < 4; i++) {
                const u64 h = h2p[i];
                P2_0 = fma2(wh2p[0][i], h, P2_0);
                P2_1 = fma2(wh2p[1][i], h, P2_1);
            }

            // ---- exchange: send other-layer partials to partner, keep own ----
            // half0's "own" layer is L1 (it runs L1 activations), half1's is L2.
            const u64 send0 = hi8 ? P1_0 : P2_0;
            const u64 send1 = hi8 ? P1_1 : P2_1;
            const u64 own0  = hi8 ? P2_0 : P1_0;
            const u64 own1  = hi8 ? P2_1 : P1_1;
            const u64 Pf0 = add2(own0, shflx8_u64(send0));
            const u64 Pf1 = add2(own1, shflx8_u64(send1));

            // ---- activation + cell chain (same code both halves) ----
            float a, b;
            upk(Pf0, a, b); const float gi = sig_h(a), gf = sig_h(b);
            upk(Pf1, a, b); const float gg = tanhap(a), go = sig_h(b);
            c = fmaf(gf, c, gi * gg);
            const float ho = go * tanhap(c);   // h1o on half0 lanes, h2o on half1

            // ---- broadcast h slices (h1 from lanes 0-7, h2 from lanes 8-15) ----
            #pragma unroll
            for (int i = 0; i < 4; i++) {
                const float v1 = __shfl_sync(0xffffffffu, ho, s1 + i, 16);
                const float v2 = __shfl_sync(0xffffffffu, ho, s2 + i, 16);
                h1p[i] = pk2(v1, v1);
                h2p[i] = pk2(v2, v2);
            }
        }
        xv = xn;
    }
    // h2(T-1) values live on lanes 8..15 of each group (unit k at lane 8+k).

    // ---- FC head: out[e][r] = b_fc[r] + sum_k Wfc[r][k]*h2[k], r < 4 ----
    {
        float h2v[8];
        const float ho_fin = ((l16 & 8) ? 1.0f : 0.0f, 0.0f);  // placeholder, unused
        (void)ho_fin;
        // gather all 8 h2 values (from dup-packed slices via shuffles)
        float own_lo;
        { float lo, hi; upk(h2p[0], lo, hi); own_lo = lo; (void)hi; }
        (void)own_lo;
        #pragma unroll
        for (int k = 0; k < 4; k++) {
            float lo, hi;
            upk(h2p[k], lo, hi); (void)hi;
            // h2p holds this thread's slice [k0, k0+4): broadcast both slices
            h2v[k0 + k] = lo;
        }
        // fetch the other half's slice from partner thread
        #pragma unroll
        for (int k = 0; k < 4; k++) {
            const float mine = h2v[k0 + k];
            const float other = __shfl_xor_sync(0xffffffffu, mine, 8, 16);
            h2v[(k0 ^ 4) + k] = other;
        }
        if (!hi8 && j < 4) {
            float acc = bfc[j];
            #pragma unroll
            for (int k = 0; k < H; k++) acc = fmaf(Wfc[j * H + k], h2v[k], acc);
            out[e * 4 + j] = acc;
        }
    }
}

extern "C" void kernel_launch(void* const* d_in, const int* in_sizes, int n_in,
                              void* d_out, int out_size)
{
    const float* x    = (const float*)d_in[0];
    const float* Wih1 = (const float*)d_in[1];
    const float* Whh1 = (const float*)d_in[2];
    const float* bih1 = (const float*)d_in[3];
    const float* bhh1 = (const float*)d_in[4];
    const float* Wih2 = (const float*)d_in[5];
    const float* Whh2 = (const float*)d_in[6];
    const float* bih2 = (const float*)d_in[7];
    const float* bhh2 = (const float*)d_in[8];
    const float* Wfc  = (const float*)d_in[9];
    const float* bfc  = (const float*)d_in[10];
    float* out = (float*)d_out;

    const int B = 4096;
    // 16 threads/element, 32-thread CTAs -> 2048 CTAs (2048 warps total)
    dim3 grid(B * 16 / 32), block(32);
    lstm2_kernel<<<grid, block>>>(x, Wih1, Whh1, bih1, bhh1,
                                  Wih2, Whh2, bih2, bhh2, Wfc, bfc, out);
}

// round 7
// speedup vs baseline: 1.3067x; 1.3067x over previous
#include <cuda_runtime.h>

// CrimeModelLSTM: 2-layer LSTM (H=8), B=4096, T=512, FC head [4,8].
// 8 threads/element (R3 shape — best measured). R7 changes vs R3:
//  (1) h2 broadcast through shared memory: one STS.64 of (h2o,h2o) per thread,
//      four LDS.128 reads give all 8 dup-pairs (replaces 8 SHFL + 8 pk2).
//  (2) S2 = sum_k wh2[k]*h2[k] precomputed at END of step t (off critical path;
//      consumed by step t+1's gate combine) -> L2 chain 16-deep -> 8 + add2.
//  (3) L1 gate chain split 2-way (+2 add2, chain 36 -> 24 cyc).
// fma.rn.f32x2 gate-pair packing, tanh.approx activations, cross-layer
// pipelining (body computes L2(t) and L1(t+1)) kept from R3.

typedef unsigned long long u64;

__device__ __forceinline__ u64 pk2(float lo, float hi) {
    u64 r; asm("mov.b64 %0, {%1,%2};" : "=l"(r) : "f"(lo), "f"(hi)); return r;
}
__device__ __forceinline__ void upk(u64 v, float& lo, float& hi) {
    asm("mov.b64 {%0,%1}, %2;" : "=f"(lo), "=f"(hi) : "l"(v));
}
__device__ __forceinline__ u64 fma2(u64 a, u64 b, u64 c) {
    u64 d; asm("fma.rn.f32x2 %0, %1, %2, %3;" : "=l"(d) : "l"(a), "l"(b), "l"(c)); return d;
}
__device__ __forceinline__ u64 mul2(u64 a, u64 b) {
    u64 d; asm("mul.rn.f32x2 %0, %1, %2;" : "=l"(d) : "l"(a), "l"(b)); return d;
}
__device__ __forceinline__ u64 add2(u64 a, u64 b) {
    u64 d; asm("add.rn.f32x2 %0, %1, %2;" : "=l"(d) : "l"(a), "l"(b)); return d;
}
__device__ __forceinline__ float tanhap(float x) {
    float r; asm("tanh.approx.f32 %0, %1;" : "=f"(r) : "f"(x)); return r;
}
// input pre-scaled by 0.5: sigmoid(2p) = 0.5 + 0.5*tanh(p)
__device__ __forceinline__ float sig_h(float p) { return fmaf(tanhap(p), 0.5f, 0.5f); }

__global__ void __launch_bounds__(32)
lstm2_kernel(const float* __restrict__ x,
             const float* __restrict__ Wih1, const float* __restrict__ Whh1,
             const float* __restrict__ bih1, const float* __restrict__ bhh1,
             const float* __restrict__ Wih2, const float* __restrict__ Whh2,
             const float* __restrict__ bih2, const float* __restrict__ bhh2,
             const float* __restrict__ Wfc,  const float* __restrict__ bfc,
             float* __restrict__ out)
{
    constexpr int T = 512;
    constexpr int H = 8;

    const int tid = blockIdx.x * 32 + threadIdx.x;
    const int e   = tid >> 3;                 // batch element
    const int j   = tid & 7;                  // hidden unit owned
    const int grp = (threadIdx.x >> 3) & 3;   // 8-lane group within CTA

    // per-group h2 dup-pair staging: hs[grp][k] = (h2[k], h2[k])
    __shared__ alignas(16) u64 hs[4][8];

    // per-gate scales: sigmoid rows (i,f,o) get 0.5 folded; tanh row (g) 1.0
    const float gsc[4] = {0.5f, 0.5f, 1.0f, 0.5f};

    // ---- weights packed as gate pairs: pair0 = (i,f), pair1 = (g,o) ----
    u64 wh1p[2][H], wi2p[2][H], wh2p[2][H];
    u64 wx1p[2], bb1p[2], bb2p[2];
    #pragma unroll
    for (int p = 0; p < 2; p++) {
        const int gA = 2 * p, gB = 2 * p + 1;
        const int rA = gA * 8 + j, rB = gB * 8 + j;
        const float sA = gsc[gA], sB = gsc[gB];
        wx1p[p] = pk2(Wih1[rA] * sA, Wih1[rB] * sB);
        bb1p[p] = pk2((bih1[rA] + bhh1[rA]) * sA, (bih1[rB] + bhh1[rB]) * sB);
        bb2p[p] = pk2((bih2[rA] + bhh2[rA]) * sA, (bih2[rB] + bhh2[rB]) * sB);
        #pragma unroll
        for (int k = 0; k < H; k++) {
            wh1p[p][k] = pk2(Whh1[rA * H + k] * sA, Whh1[rB * H + k] * sB);
            wi2p[p][k] = pk2(Wih2[rA * H + k] * sA, Wih2[rB * H + k] * sB);
            wh2p[p][k] = pk2(Whh2[rA * H + k] * sA, Whh2[rB * H + k] * sB);
        }
    }

    // ---- state ----
    u64 h1d[H];                       // h1(t) dup-packed
    #pragma unroll
    for (int k = 0; k < H; k++) h1d[k] = 0ull;
    u64 S2_0 = 0ull, S2_1 = 0ull;     // sum_k wh2[k]*h2(t-1)[k], per gate pair
    float c1 = 0.0f, c2 = 0.0f;

    const float4* __restrict__ xp = reinterpret_cast<const float4*>(x + (long)e * T);
    float4 xv = xp[0];

    // ---- prologue: L1 step 0 (h1 = 0: only x term) ----
    {
        u64 x2 = pk2(xv.x, xv.x);
        u64 P0 = fma2(wx1p[0], x2, bb1p[0]);
        u64 P1 = fma2(wx1p[1], x2, bb1p[1]);
        float a, b;
        upk(P0, a, b); const float i1 = sig_h(a), f1 = sig_h(b);
        upk(P1, a, b); const float g1 = tanhap(a), o1 = sig_h(b);
        c1 = i1 * g1;
        const float h1o = o1 * tanhap(c1);
        #pragma unroll
        for (int k = 0; k < H; k++) {
            const float v = __shfl_sync(0xffffffffu, h1o, k, 8);
            h1d[k] = pk2(v, v);
        }
    }

    // ---- main loop: body computes L2(t) and L1(t+1); both consume h1(t) ----
    for (int tt = 0; tt < T / 4; ++tt) {
        const int nxt = (tt + 1 < T / 4) ? (tt + 1) : tt;
        float4 xn = xp[nxt];
        float xs[4] = {xv.y, xv.z, xv.w, xn.x};  // x for L1 step t+1

        #pragma unroll
        for (int q = 0; q < 4; q++) {
            u64 x2 = pk2(xs[q], xs[q]);

            // ---- L1(t+1) gates, 2-way split: A (x-term + k0..3), B (k4..7)
            u64 A0 = fma2(wx1p[0], x2, bb1p[0]);
            u64 A1 = fma2(wx1p[1], x2, bb1p[1]);
            #pragma unroll
            for (int k = 0; k < 4; k++) {
                A0 = fma2(wh1p[0][k], h1d[k], A0);
                A1 = fma2(wh1p[1][k], h1d[k], A1);
            }
            u64 B0 = mul2(wh1p[0][4], h1d[4]);
            u64 B1 = mul2(wh1p[1][4], h1d[4]);
            #pragma unroll
            for (int k = 5; k < 8; k++) {
                B0 = fma2(wh1p[0][k], h1d[k], B0);
                B1 = fma2(wh1p[1][k], h1d[k], B1);
            }

            // ---- L2(t) gates: bb2 + wi2*h1(t); wh2*h2(t-1) is in S2
            u64 P20 = bb2p[0], P21 = bb2p[1];
            #pragma unroll
            for (int k = 0; k < H; k++) {
                P20 = fma2(wi2p[0][k], h1d[k], P20);
                P21 = fma2(wi2p[1][k], h1d[k], P21);
            }

            const u64 P1f0 = add2(A0, B0);
            const u64 P1f1 = add2(A1, B1);
            const u64 P2f0 = add2(P20, S2_0);
            const u64 P2f1 = add2(P21, S2_1);

            // ---- L2(t) activation chain -> h2o, stage to smem
            float a, b;
            upk(P2f0, a, b); const float i2 = sig_h(a), f2 = sig_h(b);
            upk(P2f1, a, b); const float g2 = tanhap(a), o2 = sig_h(b);
            c2 = fmaf(f2, c2, i2 * g2);
            const float h2o = o2 * tanhap(c2);
            hs[grp][j] = pk2(h2o, h2o);          // STS.64

            // ---- L1(t+1) activation chain -> h1o, broadcast via shfl
            upk(P1f0, a, b); const float i1 = sig_h(a), f1 = sig_h(b);
            upk(P1f1, a, b); const float g1 = tanhap(a), o1 = sig_h(b);
            c1 = fmaf(f1, c1, i1 * g1);
            const float h1o = o1 * tanhap(c1);
            #pragma unroll
            for (int k = 0; k < H; k++) {
                const float v = __shfl_sync(0xffffffffu, h1o, k, 8);
                h1d[k] = pk2(v, v);
            }

            // ---- S2 for next step: sum_k wh2[k]*h2(t)[k] (off critical path)
            __syncwarp();
            const ulonglong2* hp = reinterpret_cast<const ulonglong2*>(&hs[grp][0]);
            const ulonglong2 v0 = hp[0], v1 = hp[1], v2 = hp[2], v3 = hp[3];
            u64 s0 = mul2(wh2p[0][0], v0.x);
            u64 s1 = mul2(wh2p[1][0], v0.x);
            s0 = fma2(wh2p[0][1], v0.y, s0);  s1 = fma2(wh2p[1][1], v0.y, s1);
            s0 = fma2(wh2p[0][2], v1.x, s0);  s1 = fma2(wh2p[1][2], v1.x, s1);
            s0 = fma2(wh2p[0][3], v1.y, s0);  s1 = fma2(wh2p[1][3], v1.y, s1);
            s0 = fma2(wh2p[0][4], v2.x, s0);  s1 = fma2(wh2p[1][4], v2.x, s1);
            s0 = fma2(wh2p[0][5], v2.y, s0);  s1 = fma2(wh2p[1][5], v2.y, s1);
            s0 = fma2(wh2p[0][6], v3.x, s0);  s1 = fma2(wh2p[1][6], v3.x, s1);
            s0 = fma2(wh2p[0][7], v3.y, s0);  s1 = fma2(wh2p[1][7], v3.y, s1);
            S2_0 = s0;
            S2_1 = s1;
        }
        xv = xn;
    }
    // loop produced h2(T-1); smem holds (h2(T-1)[k], h2(T-1)[k]) per group.

    // ---- FC head: out[e][r] = b_fc[r] + sum_k Wfc[r][k]*h2[k], r < 4 ----
    if (j < 4) {
        const float* hf = reinterpret_cast<const float*>(&hs[grp][0]);
        float acc = bfc[j];
        #pragma unroll
        for (int k = 0; k < H; k++)
            acc = fmaf(Wfc[j * H + k], hf[2 * k], acc);
        out[e * 4 + j] = acc;
    }
}

extern "C" void kernel_launch(void* const* d_in, const int* in_sizes, int n_in,
                              void* d_out, int out_size)
{
    const float* x    = (const float*)d_in[0];
    const float* Wih1 = (const float*)d_in[1];
    const float* Whh1 = (const float*)d_in[2];
    const float* bih1 = (const float*)d_in[3];
    const float* bhh1 = (const float*)d_in[4];
    const float* Wih2 = (const float*)d_in[5];
    const float* Whh2 = (const float*)d_in[6];
    const float* bih2 = (const float*)d_in[7];
    const float* bhh2 = (const float*)d_in[8];
    const float* Wfc  = (const float*)d_in[9];
    const float* bfc  = (const float*)d_in[10];
    float* out = (float*)d_out;

    const int B = 4096;
    dim3 grid(B * 8 / 32), block(32);
    lstm2_kernel<<<grid, block>>>(x, Wih1, Whh1, bih1, bhh1,
                                  Wih2, Whh2, bih2, bhh2, Wfc, bfc, out);
}